// round 1
// baseline (speedup 1.0000x reference)
#include <cuda_runtime.h>
#include <cuda_bf16.h>

// Problem constants (DRewGIN: N=50000 nodes, E=800000 edges, D=128, L=3)
#define NMAX 50000
#define EMAX 800000
#define DIM  128
#define LAY  3

// ---------------- device scratch (static, no allocation) ----------------
__device__ float g_x1[NMAX * DIM];     // xs[1]
__device__ float g_x2[NMAX * DIM];     // xs[2]
__device__ float g_sout[NMAX * DIM];   // (1+eps)*relu(xt@Ws+bs)
__device__ float g_z0[NMAX * DIM];     // z for k=1
__device__ float g_z1[NMAX * DIM];     // z for k=2
__device__ float g_z2[NMAX * DIM];     // z for k=3
__device__ int g_count[NMAX];
__device__ int g_rowptr[NMAX + 1];
__device__ int g_wptr[NMAX];
__device__ unsigned g_edges[EMAX];     // packed: src (16 bits) | attr<<16

// ---------------- CSR build ----------------
__global__ void zero_count_k(int n) {
    int i = blockIdx.x * blockDim.x + threadIdx.x;
    if (i < n) g_count[i] = 0;
}

__global__ void count_k(const int* __restrict__ dst, int e) {
    int i = blockIdx.x * blockDim.x + threadIdx.x;
    if (i < e) atomicAdd(&g_count[dst[i]], 1);
}

__global__ void scan_k(int n, int e) {
    __shared__ int sh[1024];
    int tid = threadIdx.x;
    int ch = (n + 1023) >> 10;
    int beg = tid * ch;
    int end = beg + ch; if (end > n) end = n;
    int s = 0;
    for (int i = beg; i < end; i++) s += g_count[i];
    sh[tid] = s;
    __syncthreads();
    for (int off = 1; off < 1024; off <<= 1) {
        int v = (tid >= off) ? sh[tid - off] : 0;
        __syncthreads();
        sh[tid] += v;
        __syncthreads();
    }
    int excl = (tid == 0) ? 0 : sh[tid - 1];
    for (int i = beg; i < end; i++) {
        g_rowptr[i] = excl;
        g_wptr[i] = excl;
        excl += g_count[i];
    }
    if (tid == 0) g_rowptr[n] = e;
}

__global__ void place_k(const int* __restrict__ src, const int* __restrict__ dst,
                        const int* __restrict__ attr, int e) {
    int i = blockIdx.x * blockDim.x + threadIdx.x;
    if (i < e) {
        int pos = atomicAdd(&g_wptr[dst[i]], 1);
        g_edges[pos] = (unsigned)src[i] | ((unsigned)attr[i] << 16);
    }
}

// ---------------- GEMM: C[n x 128] = A[n x 128] @ W[128 x 128] ----------------
// mode 0: C = A@W
// mode 1: C = (1 + *epsp) * relu(A@W + bias)
__global__ void gemm_k(const float* __restrict__ A, const float* __restrict__ W,
                       const float* __restrict__ bias, const float* __restrict__ epsp,
                       float* __restrict__ C, int n, int mode) {
    __shared__ float As[16][65];
    __shared__ float Bs[16][132];
    const int br = blockIdx.x * 64;
    const int tid = threadIdx.x;       // 256 threads
    const int tx = tid & 15;           // 0..15 -> 8 cols each
    const int ty = tid >> 4;           // 0..15 -> 4 rows each

    float acc[4][8];
#pragma unroll
    for (int i = 0; i < 4; i++)
#pragma unroll
        for (int j = 0; j < 8; j++) acc[i][j] = 0.f;

    const int ar = tid >> 2;           // 0..63 (A-load row within tile)
    const int ac = (tid & 3) << 2;     // 0,4,8,12 (A-load col within BK)

    for (int k0 = 0; k0 < 128; k0 += 16) {
        // load A tile 64x16 (one float4 per thread), transposed store
        int grow = br + ar;
        float4 av = make_float4(0.f, 0.f, 0.f, 0.f);
        if (grow < n) av = *(const float4*)(A + grow * 128 + k0 + ac);
        As[ac + 0][ar] = av.x;
        As[ac + 1][ar] = av.y;
        As[ac + 2][ar] = av.z;
        As[ac + 3][ar] = av.w;
        // load B tile 16x128 (two float4 per thread)
#pragma unroll
        for (int i = 0; i < 2; i++) {
            int lin = tid + i * 256;
            int rb = lin >> 5;
            int cb = (lin & 31) << 2;
            *(float4*)&Bs[rb][cb] = *(const float4*)(W + (k0 + rb) * 128 + cb);
        }
        __syncthreads();
#pragma unroll
        for (int kk = 0; kk < 16; kk++) {
            float a[4], b[8];
#pragma unroll
            for (int i = 0; i < 4; i++) a[i] = As[kk][ty * 4 + i];
#pragma unroll
            for (int j = 0; j < 8; j++) b[j] = Bs[kk][tx * 8 + j];
#pragma unroll
            for (int i = 0; i < 4; i++)
#pragma unroll
                for (int j = 0; j < 8; j++) acc[i][j] += a[i] * b[j];
        }
        __syncthreads();
    }

    float escale = 1.0f;
    if (mode == 1) escale = 1.0f + *epsp;
#pragma unroll
    for (int i = 0; i < 4; i++) {
        int row = br + ty * 4 + i;
        if (row >= n) continue;
#pragma unroll
        for (int j = 0; j < 8; j++) {
            int col = tx * 8 + j;
            float v = acc[i][j];
            if (mode == 1) v = escale * fmaxf(v + bias[col], 0.f);
            C[row * 128 + col] = v;
        }
    }
}

// ---------------- fused aggregation + epilogue ----------------
// one warp per destination node; kmax in {1,2,3}
__device__ __forceinline__ float4 relu4(float4 v) {
    return make_float4(fmaxf(v.x, 0.f), fmaxf(v.y, 0.f), fmaxf(v.z, 0.f), fmaxf(v.w, 0.f));
}
__device__ __forceinline__ void add4(float4& a, const float4 b) {
    a.x += b.x; a.y += b.y; a.z += b.z; a.w += b.w;
}

__global__ void aggregate_k(const float* __restrict__ xt, const float* __restrict__ souts,
                            const float* __restrict__ z1, const float* __restrict__ z2,
                            const float* __restrict__ z3, const float* __restrict__ bk_t,
                            int kmax, float* __restrict__ xnext, int n) {
    int warp = (blockIdx.x * blockDim.x + threadIdx.x) >> 5;
    if (warp >= n) return;
    int lane = threadIdx.x & 31;

    float4 acc1 = make_float4(0.f, 0.f, 0.f, 0.f);
    float4 acc2 = acc1, acc3 = acc1;

    int beg = g_rowptr[warp];
    int end = g_rowptr[warp + 1];
    for (int e = beg; e < end; e++) {
        unsigned p = g_edges[e];
        int a = (int)(p >> 16);
        if (a > kmax) continue;
        int src = (int)(p & 0xFFFFu);
        const float4* zp = (const float4*)((a == 1) ? z1 : (a == 2) ? z2 : z3);
        float4 v = zp[src * 32 + lane];
        if (a == 1) add4(acc1, v);
        else if (a == 2) add4(acc2, v);
        else add4(acc3, v);
    }

    float4 o = ((const float4*)souts)[warp * 32 + lane];
    {
        float4 b = ((const float4*)(bk_t + 0 * DIM))[lane];
        add4(acc1, b);
        add4(o, relu4(acc1));
    }
    if (kmax >= 2) {
        float4 b = ((const float4*)(bk_t + 1 * DIM))[lane];
        add4(acc2, b);
        add4(o, relu4(acc2));
    }
    if (kmax >= 3) {
        float4 b = ((const float4*)(bk_t + 2 * DIM))[lane];
        add4(acc3, b);
        add4(o, relu4(acc3));
    }
    float4 xv = ((const float4*)xt)[warp * 32 + lane];
    float4 h = relu4(o);
    add4(xv, h);
    ((float4*)xnext)[warp * 32 + lane] = xv;
}

// ---------------- launch ----------------
extern "C" void kernel_launch(void* const* d_in, const int* in_sizes, int n_in,
                              void* d_out, int out_size) {
    const float* x   = (const float*)d_in[0];
    const int*   ei  = (const int*)d_in[1];   // [2, E]: row0 src, row1 dst
    const int*   ea  = (const int*)d_in[2];   // [E] in {1..3}
    const float* Ws  = (const float*)d_in[3]; // [L, D, D]
    const float* bs  = (const float*)d_in[4]; // [L, D]
    const float* Wk  = (const float*)d_in[5]; // [L, L, D, D]
    const float* bk  = (const float*)d_in[6]; // [L, L, D]
    const float* eps = (const float*)d_in[7]; // [L]
    float* out = (float*)d_out;

    int n = in_sizes[0] / DIM;
    int e = in_sizes[2];
    const int* src = ei;
    const int* dst = ei + e;

    float *p_x1, *p_x2, *p_sout, *p_z0, *p_z1, *p_z2;
    cudaGetSymbolAddress((void**)&p_x1, g_x1);
    cudaGetSymbolAddress((void**)&p_x2, g_x2);
    cudaGetSymbolAddress((void**)&p_sout, g_sout);
    cudaGetSymbolAddress((void**)&p_z0, g_z0);
    cudaGetSymbolAddress((void**)&p_z1, g_z1);
    cudaGetSymbolAddress((void**)&p_z2, g_z2);

    // ----- CSR build -----
    zero_count_k<<<(n + 255) / 256, 256>>>(n);
    count_k<<<(e + 255) / 256, 256>>>(dst, e);
    scan_k<<<1, 1024>>>(n, e);
    place_k<<<(e + 255) / 256, 256>>>(src, dst, ea, e);

    const float* xs[4];
    xs[0] = x;
    xs[1] = p_x1;
    xs[2] = p_x2;
    xs[3] = out;

    int gemm_grid = (n + 63) / 64;
    int agg_grid = (n * 32 + 255) / 256;

    for (int t = 0; t < LAY; t++) {
        // mlp_s: (1+eps)*relu(xt@Ws[t]+bs[t])
        gemm_k<<<gemm_grid, 256>>>(xs[t], Ws + (size_t)t * DIM * DIM,
                                   bs + t * DIM, eps + t, p_sout, n, 1);
        // z_k = xs[t-k+1] @ Wk[t][k-1]
        float* zbuf[3] = {p_z0, p_z1, p_z2};
        for (int k = 1; k <= t + 1; k++) {
            const float* asrc = xs[t - (k - 1)];
            const float* Wkt = Wk + ((size_t)t * LAY + (k - 1)) * DIM * DIM;
            gemm_k<<<gemm_grid, 256>>>(asrc, Wkt, nullptr, nullptr,
                                       zbuf[k - 1], n, 0);
        }
        // fused aggregate + epilogue + residual -> xs[t+1]
        aggregate_k<<<agg_grid, 256>>>(xs[t], p_sout, p_z0, p_z1, p_z2,
                                       bk + (size_t)t * LAY * DIM, t + 1,
                                       (float*)xs[t + 1], n);
    }
}